// round 4
// baseline (speedup 1.0000x reference)
#include <cuda_runtime.h>
#include <math.h>

#define NN 50000      // nodes
#define NE 800000     // edges
#define NG 128        // graphs
#define FX 92         // node feature dim
#define FE 41         // edge feature dim
#define HD 64         // hidden
#define NCV 3         // conv layers
#define BN_EPS 1e-5f
#define NBLK 196      // scan blocks: 196*256 = 50176 >= NN

typedef unsigned long long ull;
typedef long long ll;

// ---------------- device scratch ----------------
__device__ float g_h[NN * HD];
__device__ float g_acc[NN * HD];
__device__ float g_HN[NN * 4 * HD];                   // [N,256]: [f_i|s_i|f_j|s_j]
__device__ float g_Wce[NCV * FE * 2 * HD];
__device__ float g_bce[NCV * 2 * HD];
__device__ float g_Wnode[NCV * HD * 4 * HD];
__device__ float g_sum[NCV * HD];
__device__ float g_sumsq[NCV * HD];
__device__ float g_gsum[NG * HD];
__device__ float g_gcnt[NG];
// sort-by-dst machinery
__device__ int   g_deg[NN];
__device__ int   g_cursor[NN];
__device__ int   g_rp[NN];          // exclusive prefix of deg
__device__ int   g_bsum[256];
__device__ int   g_perm[NE];
__device__ int   g_srcp[NE];
__device__ int   g_dstp[NE];
__device__ float g_eap[(ll)NE * FE];   // permuted edge_attr

// ---------------- f32x2 packed math helpers ----------------
__device__ __forceinline__ ull pack2(float a, float b) {
    ull r; asm("mov.b64 %0, {%1, %2};" : "=l"(r) : "f"(a), "f"(b)); return r;
}
__device__ __forceinline__ void unpack2(ull v, float& a, float& b) {
    asm("mov.b64 {%0, %1}, %2;" : "=f"(a), "=f"(b) : "l"(v));
}
__device__ __forceinline__ void fma2(ull& d, ull a, ull b) {
    asm("fma.rn.f32x2 %0, %1, %2, %0;" : "+l"(d) : "l"(a), "l"(b));
}
__device__ __forceinline__ float sigmoid_f(float x) {
    return __fdividef(1.0f, 1.0f + __expf(-x));
}
__device__ __forceinline__ float softplus_f(float x) {
    return fmaxf(x, 0.0f) + __logf(1.0f + __expf(-fabsf(x)));
}
__device__ __forceinline__ void red4(float* p, float4 v) {
    asm volatile("red.global.add.v4.f32 [%0], {%1,%2,%3,%4};"
                 :: "l"(p), "f"(v.x), "f"(v.y), "f"(v.z), "f"(v.w) : "memory");
}

// ---------------- prep: fold weights ----------------
__global__ void prep_kernel(const float* __restrict__ W_emb2, const float* __restrict__ b_emb2,
                            const float* __restrict__ Wf, const float* __restrict__ bf,
                            const float* __restrict__ Ws, const float* __restrict__ bs) {
    int idx = blockIdx.x * blockDim.x + threadIdx.x;
    const int N_WCE = NCV * FE * 2 * HD;
    const int N_BCE = NCV * 2 * HD;
    const int N_WND = NCV * HD * 4 * HD;
    if (idx < N_WCE) {
        int j = idx % (2 * HD);
        int k = (idx / (2 * HD)) % FE;
        int a = idx / (2 * HD * FE);
        const float* Wb = (j < HD) ? Wf : Ws;
        int jj = j & (HD - 1);
        float s = 0.f;
        #pragma unroll 8
        for (int m = 0; m < HD; m++)
            s = fmaf(W_emb2[k * HD + m], Wb[(a * 3 * HD + 2 * HD + m) * HD + jj], s);
        g_Wce[idx] = s;
    } else if (idx < N_WCE + N_BCE) {
        int t = idx - N_WCE;
        int j = t % (2 * HD);
        int a = t / (2 * HD);
        const float* Wb = (j < HD) ? Wf : Ws;
        const float* bb = (j < HD) ? bf : bs;
        int jj = j & (HD - 1);
        float s = bb[a * HD + jj];
        #pragma unroll 8
        for (int m = 0; m < HD; m++)
            s = fmaf(b_emb2[m], Wb[(a * 3 * HD + 2 * HD + m) * HD + jj], s);
        g_bce[t] = s;
    } else if (idx < N_WCE + N_BCE + N_WND) {
        int t = idx - N_WCE - N_BCE;
        int j = t % (4 * HD);
        int m = (t / (4 * HD)) % HD;
        int a = t / (4 * HD * HD);
        int blk = j / HD;                 // 0:f_i 1:s_i 2:f_j 3:s_j
        int jj = j & (HD - 1);
        const float* Wsel = (blk & 1) ? Ws : Wf;
        int roff = (blk >= 2) ? HD : 0;
        g_Wnode[t] = Wsel[(a * 3 * HD + roff + m) * HD + jj];
    }
}

// ---------------- zero counters/stats ----------------
__global__ void zero_kernel() {
    int i = blockIdx.x * blockDim.x + threadIdx.x;
    if (i < NN) { g_deg[i] = 0; g_cursor[i] = 0; }
    if (i < NCV * HD) { g_sum[i] = 0.f; g_sumsq[i] = 0.f; }
    if (i < NG * HD) g_gsum[i] = 0.f;
    if (i < NG) g_gcnt[i] = 0.f;
}

// ---------------- sort by dst: histogram / scan / scatter / permute ----------------
__global__ void hist_kernel(const int* __restrict__ ei) {
    int e = blockIdx.x * blockDim.x + threadIdx.x;
    if (e < NE) atomicAdd(&g_deg[ei[NE + e]], 1);
}
__global__ void scan1_kernel() {
    __shared__ int s[256];
    int tid = threadIdx.x;
    int i = blockIdx.x * 256 + tid;
    int v = (i < NN) ? g_deg[i] : 0;
    s[tid] = v; __syncthreads();
    #pragma unroll
    for (int off = 1; off < 256; off <<= 1) {
        int t = (tid >= off) ? s[tid - off] : 0;
        __syncthreads();
        s[tid] += t;
        __syncthreads();
    }
    if (i < NN) g_rp[i] = s[tid] - v;
    if (tid == 255) g_bsum[blockIdx.x] = s[255];
}
__global__ void scan2_kernel() {
    __shared__ int s[256];
    int tid = threadIdx.x;
    int v = (tid < NBLK) ? g_bsum[tid] : 0;
    s[tid] = v; __syncthreads();
    #pragma unroll
    for (int off = 1; off < 256; off <<= 1) {
        int t = (tid >= off) ? s[tid - off] : 0;
        __syncthreads();
        s[tid] += t;
        __syncthreads();
    }
    if (tid < NBLK) g_bsum[tid] = s[tid] - v;
}
__global__ void scan3_kernel() {
    int i = blockIdx.x * 256 + threadIdx.x;
    if (i < NN) g_rp[i] += g_bsum[blockIdx.x];
}
__global__ void scatter_kernel(const int* __restrict__ ei) {
    int e = blockIdx.x * blockDim.x + threadIdx.x;
    if (e >= NE) return;
    int d = ei[NE + e];
    int s = ei[e];
    int pos = g_rp[d] + atomicAdd(&g_cursor[d], 1);
    g_perm[pos] = e;
    g_srcp[pos] = s;
    g_dstp[pos] = d;
}
__global__ void permute_ea_kernel(const float* __restrict__ ea) {
    int w = (blockIdx.x * blockDim.x + threadIdx.x) >> 5;
    int lane = threadIdx.x & 31;
    int nw = (gridDim.x * blockDim.x) >> 5;
    for (int row = w; row < NE; row += nw) {
        int e = g_perm[row];
        #pragma unroll
        for (int k = lane; k < FE; k += 32)
            g_eap[(ll)row * FE + k] = ea[(ll)e * FE + k];
    }
}

// ---------------- generic fp32 GEMM with f32x2 inner loop ----------------
template <int K, int NC, int CT, int RT, int RPT>
__global__ void gemm_bias_kernel(const float* __restrict__ A, const float* __restrict__ B,
                                 const float* __restrict__ bias, float* __restrict__ C,
                                 int M, int ldb, int ldc) {
    constexpr int TR = RT * RPT;
    constexpr int KP = K + 1;
    constexpr int NT = CT * RT;
    extern __shared__ float smem[];
    float* Bs = smem;
    float* As = smem + K * NC;
    int tid = threadIdx.x;
    int tx = tid % CT;
    int ty = tid / CT;
    int c0 = blockIdx.y * NC;
    for (int i = tid; i < K * NC; i += NT) {
        int k = i / NC, c = i - k * NC;
        Bs[i] = B[k * ldb + c0 + c];
    }
    ull bp[4];
    #pragma unroll
    for (int c = 0; c < 4; c++) {
        float b0 = bias ? bias[c0 + tx * 8 + 2 * c] : 0.f;
        float b1 = bias ? bias[c0 + tx * 8 + 2 * c + 1] : 0.f;
        bp[c] = pack2(b0, b1);
    }
    for (int tile = blockIdx.x; (ll)tile * TR < M; tile += gridDim.x) {
        int row0 = tile * TR;
        __syncthreads();
        for (int i = tid; i < TR * K; i += NT) {
            int r = i / K;
            int k = i - r * K;
            int gr = row0 + r;
            As[r * KP + k] = (gr < M) ? A[(ll)gr * K + k] : 0.f;
        }
        __syncthreads();
        ull acc[RPT][4];
        #pragma unroll
        for (int r = 0; r < RPT; r++)
            #pragma unroll
            for (int c = 0; c < 4; c++) acc[r][c] = bp[c];
        for (int k = 0; k < K; k++) {
            float4 b0 = *reinterpret_cast<const float4*>(&Bs[k * NC + tx * 8]);
            float4 b1 = *reinterpret_cast<const float4*>(&Bs[k * NC + tx * 8 + 4]);
            ull p0 = pack2(b0.x, b0.y), p1 = pack2(b0.z, b0.w);
            ull p2 = pack2(b1.x, b1.y), p3 = pack2(b1.z, b1.w);
            #pragma unroll
            for (int r = 0; r < RPT; r++) {
                float a = As[(ty * RPT + r) * KP + k];
                ull ad = pack2(a, a);
                fma2(acc[r][0], ad, p0);
                fma2(acc[r][1], ad, p1);
                fma2(acc[r][2], ad, p2);
                fma2(acc[r][3], ad, p3);
            }
        }
        #pragma unroll
        for (int r = 0; r < RPT; r++) {
            int gr = row0 + ty * RPT + r;
            if (gr < M) {
                float o[8];
                #pragma unroll
                for (int c = 0; c < 4; c++) unpack2(acc[r][c], o[2 * c], o[2 * c + 1]);
                float* cp = &C[(ll)gr * ldc + c0 + tx * 8];
                *reinterpret_cast<float4*>(cp) = make_float4(o[0], o[1], o[2], o[3]);
                *reinterpret_cast<float4*>(cp + 4) = make_float4(o[4], o[5], o[6], o[7]);
            }
        }
    }
}

// ---------------- residual copy ----------------
__global__ void copy_kernel() {
    int idx4 = blockIdx.x * blockDim.x + threadIdx.x;
    if (idx4 < NN * 16)
        reinterpret_cast<float4*>(g_acc)[idx4] = reinterpret_cast<const float4*>(g_h)[idx4];
}

// ---------------- fused: edge GEMM + message + run-compressed scatter ----------------
// edges pre-sorted by dst; g_eap rows linear.
#define EPB 128
__global__ __launch_bounds__(256) void fused_edge_kernel(
        const float* __restrict__ Wce, const float* __restrict__ bce) {
    __shared__ float Ws_s[FE * 2 * HD];
    __shared__ float A_s[EPB][FE + 1];
    __shared__ int   src_s[EPB], dst_s[EPB];
    int tid = threadIdx.x;
    int tx = tid & 15, ty = tid >> 4;
    for (int i = tid; i < FE * 2 * HD; i += 256) Ws_s[i] = Wce[i];
    float4 bf4 = *reinterpret_cast<const float4*>(&bce[tx * 4]);
    float4 bs4 = *reinterpret_cast<const float4*>(&bce[HD + tx * 4]);
    ull bf0 = pack2(bf4.x, bf4.y), bf1 = pack2(bf4.z, bf4.w);
    ull bs0 = pack2(bs4.x, bs4.y), bs1 = pack2(bs4.z, bs4.w);

    const float4* HN4 = reinterpret_cast<const float4*>(g_HN);
    const int ntiles = NE / EPB;
    for (int tile = blockIdx.x; tile < ntiles; tile += gridDim.x) {
        int e0 = tile * EPB;
        __syncthreads();
        for (int i = tid; i < EPB * FE; i += 256) {
            int r = i / FE, k = i - r * FE;
            A_s[r][k] = g_eap[(ll)e0 * FE + i];
        }
        if (tid < EPB) {
            src_s[tid] = g_srcp[e0 + tid];
            dst_s[tid] = g_dstp[e0 + tid];
        }
        __syncthreads();

        // EW tile in registers (f32x2)
        ull af[8][2], as_[8][2];
        #pragma unroll
        for (int r = 0; r < 8; r++) {
            af[r][0] = bf0; af[r][1] = bf1;
            as_[r][0] = bs0; as_[r][1] = bs1;
        }
        for (int k = 0; k < FE; k++) {
            float4 wf = *reinterpret_cast<const float4*>(&Ws_s[k * 128 + tx * 4]);
            float4 ws = *reinterpret_cast<const float4*>(&Ws_s[k * 128 + HD + tx * 4]);
            ull wf0 = pack2(wf.x, wf.y), wf1 = pack2(wf.z, wf.w);
            ull ws0 = pack2(ws.x, ws.y), ws1 = pack2(ws.z, ws.w);
            #pragma unroll
            for (int r = 0; r < 8; r++) {
                float a = A_s[ty * 8 + r][k];
                ull ad = pack2(a, a);
                fma2(af[r][0], ad, wf0);
                fma2(af[r][1], ad, wf1);
                fma2(as_[r][0], ad, ws0);
                fma2(as_[r][1], ad, ws1);
            }
        }

        // gather + activations + run-compressed scatter
        int dprev = -1;
        float4 fi, si, accm;
        #pragma unroll
        for (int r = 0; r < 8; r++) {
            int er = ty * 8 + r;
            int d = dst_s[er];
            int s = src_s[er];
            if (d != dprev) {
                if (dprev >= 0) red4(&g_acc[(ll)dprev * HD + tx * 4], accm);
                fi = HN4[(ll)d * 64 + tx];
                si = HN4[(ll)d * 64 + 16 + tx];
                accm = make_float4(0.f, 0.f, 0.f, 0.f);
                dprev = d;
            }
            float4 fj = HN4[(ll)s * 64 + 32 + tx];
            float4 sj = HN4[(ll)s * 64 + 48 + tx];
            float f0, f1, f2, f3, s0, s1, s2, s3;
            unpack2(af[r][0], f0, f1); unpack2(af[r][1], f2, f3);
            unpack2(as_[r][0], s0, s1); unpack2(as_[r][1], s2, s3);
            accm.x += sigmoid_f(f0 + fi.x + fj.x) * softplus_f(s0 + si.x + sj.x);
            accm.y += sigmoid_f(f1 + fi.y + fj.y) * softplus_f(s1 + si.y + sj.y);
            accm.z += sigmoid_f(f2 + fi.z + fj.z) * softplus_f(s2 + si.z + sj.z);
            accm.w += sigmoid_f(f3 + fi.w + fj.w) * softplus_f(s3 + si.w + sj.w);
        }
        if (dprev >= 0) red4(&g_acc[(ll)dprev * HD + tx * 4], accm);
    }
}

// ---------------- BN stats ----------------
__global__ void stats_kernel(int a) {
    __shared__ float s_s[HD], s_q[HD];
    int tid = threadIdx.x;
    if (tid < HD) { s_s[tid] = 0.f; s_q[tid] = 0.f; }
    __syncthreads();
    int col4 = tid & 15;
    float4 ls = make_float4(0.f, 0.f, 0.f, 0.f), lq = ls;
    const float4* acc4 = reinterpret_cast<const float4*>(g_acc);
    for (int idx4 = blockIdx.x * blockDim.x + tid; idx4 < NN * 16; idx4 += gridDim.x * blockDim.x) {
        float4 v = acc4[idx4];
        ls.x += v.x; lq.x = fmaf(v.x, v.x, lq.x);
        ls.y += v.y; lq.y = fmaf(v.y, v.y, lq.y);
        ls.z += v.z; lq.z = fmaf(v.z, v.z, lq.z);
        ls.w += v.w; lq.w = fmaf(v.w, v.w, lq.w);
    }
    atomicAdd(&s_s[col4 * 4 + 0], ls.x); atomicAdd(&s_q[col4 * 4 + 0], lq.x);
    atomicAdd(&s_s[col4 * 4 + 1], ls.y); atomicAdd(&s_q[col4 * 4 + 1], lq.y);
    atomicAdd(&s_s[col4 * 4 + 2], ls.z); atomicAdd(&s_q[col4 * 4 + 2], lq.z);
    atomicAdd(&s_s[col4 * 4 + 3], ls.w); atomicAdd(&s_q[col4 * 4 + 3], lq.w);
    __syncthreads();
    if (tid < HD) {
        atomicAdd(&g_sum[a * HD + tid], s_s[tid]);
        atomicAdd(&g_sumsq[a * HD + tid], s_q[tid]);
    }
}

// ---------------- BN normalize (+relu) (+next residual) (+pooling) ----------------
__global__ void bn_kernel(const float* __restrict__ gamma, const float* __restrict__ beta,
                          int a, int do_relu, int write_acc, int do_pool,
                          const int* __restrict__ batch) {
    int idx4 = blockIdx.x * blockDim.x + threadIdx.x;
    if (idx4 >= NN * 16) return;
    int col4 = idx4 & 15;
    int node = idx4 >> 4;
    const float invn = 1.0f / (float)NN;
    float4 su = reinterpret_cast<const float4*>(g_sum)[a * 16 + col4];
    float4 sq = reinterpret_cast<const float4*>(g_sumsq)[a * 16 + col4];
    float4 ga = reinterpret_cast<const float4*>(gamma)[col4];
    float4 be = reinterpret_cast<const float4*>(beta)[col4];
    float4 v = reinterpret_cast<const float4*>(g_acc)[idx4];
    #pragma unroll
    for (int c = 0; c < 4; c++) {
        float mu = (&su.x)[c] * invn;
        float var = fmaxf((&sq.x)[c] * invn - mu * mu, 0.f);
        float y = ((&v.x)[c] - mu) * rsqrtf(var + BN_EPS) * (&ga.x)[c] + (&be.x)[c];
        if (do_relu) y = fmaxf(y, 0.f);
        (&v.x)[c] = y;
    }
    reinterpret_cast<float4*>(g_h)[idx4] = v;
    if (write_acc) reinterpret_cast<float4*>(g_acc)[idx4] = v;
    if (do_pool) {
        int b = batch[node];
        red4(&g_gsum[b * HD + col4 * 4], v);
        if (col4 == 0) atomicAdd(&g_gcnt[b], 1.0f);
    }
}

// ---------------- final MLP ----------------
__global__ void mlp_kernel(const float* __restrict__ W1, const float* __restrict__ b1,
                           const float* __restrict__ W2, const float* __restrict__ b2,
                           const float* __restrict__ Wo, const float* __restrict__ bo,
                           float* __restrict__ out) {
    __shared__ float sW1[HD * HD], sW2[HD * HD], sWo[HD], sb1[HD], sb2[HD];
    int tid = threadIdx.x;
    for (int i = tid; i < HD * HD; i += blockDim.x) { sW1[i] = W1[i]; sW2[i] = W2[i]; }
    if (tid < HD) { sWo[tid] = Wo[tid]; sb1[tid] = b1[tid]; sb2[tid] = b2[tid]; }
    __syncthreads();
    if (tid < NG) {
        float inv = 1.0f / fmaxf(g_gcnt[tid], 1.0f);
        float v[HD], y[HD];
        #pragma unroll
        for (int k = 0; k < HD; k++) v[k] = g_gsum[tid * HD + k] * inv;
        #pragma unroll 1
        for (int j = 0; j < HD; j++) {
            float s = sb1[j];
            #pragma unroll
            for (int k = 0; k < HD; k++) s = fmaf(v[k], sW1[k * HD + j], s);
            y[j] = softplus_f(s);
        }
        float o = bo[0];
        #pragma unroll 1
        for (int j = 0; j < HD; j++) {
            float s = sb2[j];
            #pragma unroll
            for (int k = 0; k < HD; k++) s = fmaf(y[k], sW2[k * HD + j], s);
            o = fmaf(softplus_f(s), sWo[j], o);
        }
        out[tid] = o;
    }
}

// ---------------- host launcher ----------------
template <int K, int NC, int CT, int RT, int RPT>
static void launch_gemm(const float* A, const float* B, const float* bias, float* C,
                        int M, int ldb, int ldc, int nsplit) {
    constexpr int TR = RT * RPT;
    constexpr int KP = K + 1;
    static_assert(CT * 8 == NC, "col threads x 8 must equal NC");
    size_t sm = (size_t)(K * NC + TR * KP) * sizeof(float);
    if (sm > 48 * 1024) {
        cudaFuncSetAttribute(gemm_bias_kernel<K, NC, CT, RT, RPT>,
                             cudaFuncAttributeMaxDynamicSharedMemorySize, (int)sm);
    }
    dim3 grid((M + TR - 1) / TR, nsplit);
    gemm_bias_kernel<K, NC, CT, RT, RPT><<<grid, CT * RT, sm>>>(A, B, bias, C, M, ldb, ldc);
}

extern "C" void kernel_launch(void* const* d_in, const int* in_sizes, int n_in,
                              void* d_out, int out_size) {
    const float* x         = (const float*)d_in[0];
    const float* edge_attr = (const float*)d_in[1];
    const int*   ei        = (const int*)d_in[2];
    const int*   batch     = (const int*)d_in[3];
    const float* W_emb1    = (const float*)d_in[4];
    const float* b_emb1    = (const float*)d_in[5];
    const float* W_emb2    = (const float*)d_in[6];
    const float* b_emb2    = (const float*)d_in[7];
    const float* Wf        = (const float*)d_in[8];
    const float* bf        = (const float*)d_in[9];
    const float* Ws        = (const float*)d_in[10];
    const float* bs        = (const float*)d_in[11];
    const float* gamma     = (const float*)d_in[12];
    const float* beta      = (const float*)d_in[13];
    const float* W1        = (const float*)d_in[14];
    const float* b1        = (const float*)d_in[15];
    const float* W2        = (const float*)d_in[16];
    const float* b2        = (const float*)d_in[17];
    const float* Wo        = (const float*)d_in[18];
    const float* bo        = (const float*)d_in[19];
    float* out = (float*)d_out;

    float *p_h, *p_Wce, *p_bce, *p_Wnode;
    cudaGetSymbolAddress((void**)&p_h, g_h);
    cudaGetSymbolAddress((void**)&p_Wce, g_Wce);
    cudaGetSymbolAddress((void**)&p_bce, g_bce);
    cudaGetSymbolAddress((void**)&p_Wnode, g_Wnode);
    float* p_HN;
    cudaGetSymbolAddress((void**)&p_HN, g_HN);

    // fold weights + zero counters/stats
    prep_kernel<<<255, 256>>>(W_emb2, b_emb2, Wf, bf, Ws, bs);
    zero_kernel<<<NBLK, 256>>>();

    // sort edges by dst (counting sort) + permute edge_attr
    hist_kernel<<<(NE + 255) / 256, 256>>>(ei);
    scan1_kernel<<<NBLK, 256>>>();
    scan2_kernel<<<1, 256>>>();
    scan3_kernel<<<NBLK, 256>>>();
    scatter_kernel<<<(NE + 255) / 256, 256>>>(ei);
    permute_ea_kernel<<<1600, 256>>>(edge_attr);

    // h0 = x @ W_emb1 + b_emb1
    launch_gemm<FX, HD, 8, 32, 4>(x, W_emb1, b_emb1, p_h, NN, HD, HD, 1);
    copy_kernel<<<(NN * 16 + 255) / 256, 256>>>();

    for (int a = 0; a < NCV; a++) {
        launch_gemm<HD, 2 * HD, 16, 16, 8>(p_h, p_Wnode + (ll)a * HD * 4 * HD,
                                           nullptr, p_HN, NN, 4 * HD, 4 * HD, 2);
        fused_edge_kernel<<<888, 256>>>(p_Wce + a * FE * 2 * HD, p_bce + a * 2 * HD);
        stats_kernel<<<296, 256>>>(a);
        bn_kernel<<<(NN * 16 + 255) / 256, 256>>>(gamma + a * HD, beta + a * HD, a,
                                                  a < NCV - 1 ? 1 : 0,
                                                  a < NCV - 1 ? 1 : 0,
                                                  a == NCV - 1 ? 1 : 0, batch);
    }

    mlp_kernel<<<1, 128>>>(W1, b1, W2, b2, Wo, bo, out);
}

// round 5
// speedup vs baseline: 1.3142x; 1.3142x over previous
#include <cuda_runtime.h>
#include <math.h>

#define NN 50000      // nodes
#define NE 800000     // edges
#define NG 128        // graphs
#define FX 92         // node feature dim
#define FE 41         // edge feature dim
#define HD 64         // hidden
#define NCV 3         // conv layers
#define BN_EPS 1e-5f
#define NBLK 196      // scan blocks: 196*256 = 50176 >= NN

typedef unsigned long long ull;
typedef long long ll;

// ---------------- device scratch ----------------
__device__ float g_h[NN * HD];
__device__ float g_acc[NN * HD];
__device__ float g_HN[NN * 4 * HD];                   // [N,256]: [f_i|s_i|f_j|s_j]
__device__ float g_Wce[NCV * FE * 2 * HD];
__device__ float g_bce[NCV * 2 * HD];
__device__ float g_Wnode[NCV * HD * 4 * HD];
__device__ float g_sum[NCV * HD];
__device__ float g_sumsq[NCV * HD];
__device__ float g_gsum[NG * HD];
__device__ float g_gcnt[NG];
// sort-by-dst machinery
__device__ int   g_deg[NN];
__device__ int   g_cursor[NN];
__device__ int   g_rp[NN];
__device__ int   g_bsum[256];
__device__ int   g_perm[NE];
__device__ int   g_srcp[NE];
__device__ int   g_dstp[NE];
__device__ float g_eap[(ll)NE * FE];   // permuted edge_attr

// ---------------- f32x2 packed math helpers ----------------
__device__ __forceinline__ ull pack2(float a, float b) {
    ull r; asm("mov.b64 %0, {%1, %2};" : "=l"(r) : "f"(a), "f"(b)); return r;
}
__device__ __forceinline__ void unpack2(ull v, float& a, float& b) {
    asm("mov.b64 {%0, %1}, %2;" : "=f"(a), "=f"(b) : "l"(v));
}
__device__ __forceinline__ void fma2(ull& d, ull a, ull b) {
    asm("fma.rn.f32x2 %0, %1, %2, %0;" : "+l"(d) : "l"(a), "l"(b));
}
__device__ __forceinline__ float sigmoid_f(float x) {
    return __fdividef(1.0f, 1.0f + __expf(-x));
}
__device__ __forceinline__ float softplus_f(float x) {
    return fmaxf(x, 0.0f) + __logf(1.0f + __expf(-fabsf(x)));
}
__device__ __forceinline__ void red4(float* p, float4 v) {
    asm volatile("red.global.add.v4.f32 [%0], {%1,%2,%3,%4};"
                 :: "l"(p), "f"(v.x), "f"(v.y), "f"(v.z), "f"(v.w) : "memory");
}
__device__ __forceinline__ void red2(float* p, float a, float b) {
    asm volatile("red.global.add.v2.f32 [%0], {%1,%2};"
                 :: "l"(p), "f"(a), "f"(b) : "memory");
}

// ---------------- prep: fold weights ----------------
__global__ void prep_kernel(const float* __restrict__ W_emb2, const float* __restrict__ b_emb2,
                            const float* __restrict__ Wf, const float* __restrict__ bf,
                            const float* __restrict__ Ws, const float* __restrict__ bs) {
    int idx = blockIdx.x * blockDim.x + threadIdx.x;
    const int N_WCE = NCV * FE * 2 * HD;
    const int N_BCE = NCV * 2 * HD;
    const int N_WND = NCV * HD * 4 * HD;
    if (idx < N_WCE) {
        int j = idx % (2 * HD);
        int k = (idx / (2 * HD)) % FE;
        int a = idx / (2 * HD * FE);
        const float* Wb = (j < HD) ? Wf : Ws;
        int jj = j & (HD - 1);
        float s = 0.f;
        #pragma unroll 8
        for (int m = 0; m < HD; m++)
            s = fmaf(W_emb2[k * HD + m], Wb[(a * 3 * HD + 2 * HD + m) * HD + jj], s);
        g_Wce[idx] = s;
    } else if (idx < N_WCE + N_BCE) {
        int t = idx - N_WCE;
        int j = t % (2 * HD);
        int a = t / (2 * HD);
        const float* Wb = (j < HD) ? Wf : Ws;
        const float* bb = (j < HD) ? bf : bs;
        int jj = j & (HD - 1);
        float s = bb[a * HD + jj];
        #pragma unroll 8
        for (int m = 0; m < HD; m++)
            s = fmaf(b_emb2[m], Wb[(a * 3 * HD + 2 * HD + m) * HD + jj], s);
        g_bce[t] = s;
    } else if (idx < N_WCE + N_BCE + N_WND) {
        int t = idx - N_WCE - N_BCE;
        int j = t % (4 * HD);
        int m = (t / (4 * HD)) % HD;
        int a = t / (4 * HD * HD);
        int blk = j / HD;                 // 0:f_i 1:s_i 2:f_j 3:s_j
        int jj = j & (HD - 1);
        const float* Wsel = (blk & 1) ? Ws : Wf;
        int roff = (blk >= 2) ? HD : 0;
        g_Wnode[t] = Wsel[(a * 3 * HD + roff + m) * HD + jj];
    }
}

// ---------------- zero counters/stats ----------------
__global__ void zero_kernel() {
    int i = blockIdx.x * blockDim.x + threadIdx.x;
    if (i < NN) { g_deg[i] = 0; g_cursor[i] = 0; }
    if (i < NCV * HD) { g_sum[i] = 0.f; g_sumsq[i] = 0.f; }
    if (i < NG * HD) g_gsum[i] = 0.f;
    if (i < NG) g_gcnt[i] = 0.f;
}

// ---------------- sort by dst: histogram / scan / scatter / permute ----------------
__global__ void hist_kernel(const int* __restrict__ ei) {
    int e = blockIdx.x * blockDim.x + threadIdx.x;
    if (e < NE) atomicAdd(&g_deg[ei[NE + e]], 1);
}
__global__ void scan1_kernel() {
    __shared__ int s[256];
    int tid = threadIdx.x;
    int i = blockIdx.x * 256 + tid;
    int v = (i < NN) ? g_deg[i] : 0;
    s[tid] = v; __syncthreads();
    #pragma unroll
    for (int off = 1; off < 256; off <<= 1) {
        int t = (tid >= off) ? s[tid - off] : 0;
        __syncthreads();
        s[tid] += t;
        __syncthreads();
    }
    if (i < NN) g_rp[i] = s[tid] - v;
    if (tid == 255) g_bsum[blockIdx.x] = s[255];
}
__global__ void scan2_kernel() {
    __shared__ int s[256];
    int tid = threadIdx.x;
    int v = (tid < NBLK) ? g_bsum[tid] : 0;
    s[tid] = v; __syncthreads();
    #pragma unroll
    for (int off = 1; off < 256; off <<= 1) {
        int t = (tid >= off) ? s[tid - off] : 0;
        __syncthreads();
        s[tid] += t;
        __syncthreads();
    }
    if (tid < NBLK) g_bsum[tid] = s[tid] - v;
}
__global__ void scan3_kernel() {
    int i = blockIdx.x * 256 + threadIdx.x;
    if (i < NN) g_rp[i] += g_bsum[blockIdx.x];
}
__global__ void scatter_kernel(const int* __restrict__ ei) {
    int e = blockIdx.x * blockDim.x + threadIdx.x;
    if (e >= NE) return;
    int d = ei[NE + e];
    int s = ei[e];
    int pos = g_rp[d] + atomicAdd(&g_cursor[d], 1);
    g_perm[pos] = e;
    g_srcp[pos] = s;
    g_dstp[pos] = d;
}
__global__ void permute_ea_kernel(const float* __restrict__ ea) {
    int w = (blockIdx.x * blockDim.x + threadIdx.x) >> 5;
    int lane = threadIdx.x & 31;
    int nw = (gridDim.x * blockDim.x) >> 5;
    for (int row = w; row < NE; row += nw) {
        int e = g_perm[row];
        for (int k = lane; k < FE; k += 32)
            g_eap[(ll)row * FE + k] = ea[(ll)e * FE + k];
    }
}

// ---------------- generic fp32 GEMM with f32x2 inner loop ----------------
template <int K, int NC, int CT, int RT, int RPT>
__global__ void gemm_bias_kernel(const float* __restrict__ A, const float* __restrict__ B,
                                 const float* __restrict__ bias, float* __restrict__ C,
                                 int M, int ldb, int ldc) {
    constexpr int TR = RT * RPT;
    constexpr int KP = K + 1;
    constexpr int NT = CT * RT;
    extern __shared__ float smem[];
    float* Bs = smem;
    float* As = smem + K * NC;
    int tid = threadIdx.x;
    int tx = tid % CT;
    int ty = tid / CT;
    int c0 = blockIdx.y * NC;
    for (int i = tid; i < K * NC; i += NT) {
        int k = i / NC, c = i - k * NC;
        Bs[i] = B[k * ldb + c0 + c];
    }
    ull bp[4];
    #pragma unroll
    for (int c = 0; c < 4; c++) {
        float b0 = bias ? bias[c0 + tx * 8 + 2 * c] : 0.f;
        float b1 = bias ? bias[c0 + tx * 8 + 2 * c + 1] : 0.f;
        bp[c] = pack2(b0, b1);
    }
    for (int tile = blockIdx.x; (ll)tile * TR < M; tile += gridDim.x) {
        int row0 = tile * TR;
        __syncthreads();
        for (int i = tid; i < TR * K; i += NT) {
            int r = i / K;
            int k = i - r * K;
            int gr = row0 + r;
            As[r * KP + k] = (gr < M) ? A[(ll)gr * K + k] : 0.f;
        }
        __syncthreads();
        ull acc[RPT][4];
        #pragma unroll
        for (int r = 0; r < RPT; r++)
            #pragma unroll
            for (int c = 0; c < 4; c++) acc[r][c] = bp[c];
        for (int k = 0; k < K; k++) {
            float4 b0 = *reinterpret_cast<const float4*>(&Bs[k * NC + tx * 8]);
            float4 b1 = *reinterpret_cast<const float4*>(&Bs[k * NC + tx * 8 + 4]);
            ull p0 = pack2(b0.x, b0.y), p1 = pack2(b0.z, b0.w);
            ull p2 = pack2(b1.x, b1.y), p3 = pack2(b1.z, b1.w);
            #pragma unroll
            for (int r = 0; r < RPT; r++) {
                float a = As[(ty * RPT + r) * KP + k];
                ull ad = pack2(a, a);
                fma2(acc[r][0], ad, p0);
                fma2(acc[r][1], ad, p1);
                fma2(acc[r][2], ad, p2);
                fma2(acc[r][3], ad, p3);
            }
        }
        #pragma unroll
        for (int r = 0; r < RPT; r++) {
            int gr = row0 + ty * RPT + r;
            if (gr < M) {
                float o[8];
                #pragma unroll
                for (int c = 0; c < 4; c++) unpack2(acc[r][c], o[2 * c], o[2 * c + 1]);
                float* cp = &C[(ll)gr * ldc + c0 + tx * 8];
                *reinterpret_cast<float4*>(cp) = make_float4(o[0], o[1], o[2], o[3]);
                *reinterpret_cast<float4*>(cp + 4) = make_float4(o[4], o[5], o[6], o[7]);
            }
        }
    }
}

// ---------------- residual copy ----------------
__global__ void copy_kernel() {
    int idx4 = blockIdx.x * blockDim.x + threadIdx.x;
    if (idx4 < NN * 16)
        reinterpret_cast<float4*>(g_acc)[idx4] = reinterpret_cast<const float4*>(g_h)[idx4];
}

// ---------------- fused: edge GEMM (phase 1) + EW smem + CSR message (phase 2) ----
// edges sorted by dst; tile = 64 edges.
#define EPB 64
#define APAD 68              // A_s row stride (transposed [k][edge]), 272B: 16B-aligned
__global__ __launch_bounds__(256) void fused_edge_kernel(
        const float* __restrict__ Wce, const float* __restrict__ bce) {
    extern __shared__ float sm[];
    float* Ws_s = sm;                          // FE*128   = 5248 floats
    float* A_s  = Ws_s + FE * 128;             // FE*APAD  = 2788 floats (A^T: [k][edge])
    float* EW_s = A_s + FE * APAD;             // EPB*128  = 8192 floats
    int*   src_s = (int*)(EW_s + EPB * 128);
    int*   dst_s = src_s + EPB;

    int tid = threadIdx.x;
    int tx = tid & 15, ty = tid >> 4;
    int lane = tid & 31, wid = tid >> 5;
    for (int i = tid; i < FE * 128; i += 256) Ws_s[i] = Wce[i];
    float4 bf4 = *reinterpret_cast<const float4*>(&bce[tx * 4]);
    float4 bs4 = *reinterpret_cast<const float4*>(&bce[HD + tx * 4]);
    ull bf0 = pack2(bf4.x, bf4.y), bf1 = pack2(bf4.z, bf4.w);
    ull bs0 = pack2(bs4.x, bs4.y), bs1 = pack2(bs4.z, bs4.w);

    const int ntiles = NE / EPB;   // 12500
    for (int tile = blockIdx.x; tile < ntiles; tile += gridDim.x) {
        int e0 = tile * EPB;
        __syncthreads();   // previous message phase done before smem overwrite
        // stage A transposed: A_s[k][r] = eap[e0+r][k]
        for (int i = tid; i < EPB * FE; i += 256) {
            int r = i / FE, k = i - r * FE;
            A_s[k * APAD + r] = g_eap[(ll)e0 * FE + i];
        }
        if (tid < EPB) {
            src_s[tid] = g_srcp[e0 + tid];
            dst_s[tid] = g_dstp[e0 + tid];
        }
        __syncthreads();

        // ---- phase 1: EW tile GEMM (thread: 4 edges x 8 cols) -> smem ----
        {
            ull af[4][2], as_[4][2];
            #pragma unroll
            for (int r = 0; r < 4; r++) {
                af[r][0] = bf0; af[r][1] = bf1;
                as_[r][0] = bs0; as_[r][1] = bs1;
            }
            for (int k = 0; k < FE; k++) {
                float4 wf = *reinterpret_cast<const float4*>(&Ws_s[k * 128 + tx * 4]);
                float4 ws = *reinterpret_cast<const float4*>(&Ws_s[k * 128 + HD + tx * 4]);
                ull wf0 = pack2(wf.x, wf.y), wf1 = pack2(wf.z, wf.w);
                ull ws0 = pack2(ws.x, ws.y), ws1 = pack2(ws.z, ws.w);
                float4 a4 = *reinterpret_cast<const float4*>(&A_s[k * APAD + ty * 4]);
                #pragma unroll
                for (int r = 0; r < 4; r++) {
                    float a = (&a4.x)[r];
                    ull ad = pack2(a, a);
                    fma2(af[r][0], ad, wf0);
                    fma2(af[r][1], ad, wf1);
                    fma2(as_[r][0], ad, ws0);
                    fma2(as_[r][1], ad, ws1);
                }
            }
            #pragma unroll
            for (int r = 0; r < 4; r++) {
                float o0, o1, o2, o3;
                unpack2(af[r][0], o0, o1); unpack2(af[r][1], o2, o3);
                *reinterpret_cast<float4*>(&EW_s[(ty * 4 + r) * 128 + tx * 4]) =
                    make_float4(o0, o1, o2, o3);
                unpack2(as_[r][0], o0, o1); unpack2(as_[r][1], o2, o3);
                *reinterpret_cast<float4*>(&EW_s[(ty * 4 + r) * 128 + HD + tx * 4]) =
                    make_float4(o0, o1, o2, o3);
            }
        }
        __syncthreads();

        // ---- phase 2: message + run-compressed scatter (warp: 8 edges, uniform dst) ----
        {
            int dprev = -1;
            float fi0 = 0.f, fi1 = 0.f, si0 = 0.f, si1 = 0.f, a0 = 0.f, a1 = 0.f;
            #pragma unroll
            for (int r = 0; r < 8; r++) {
                int e = wid * 8 + r;
                int d = dst_s[e];          // warp-uniform
                int s = src_s[e];          // warp-uniform
                if (d != dprev) {
                    if (dprev >= 0) red2(&g_acc[(ll)dprev * HD + 2 * lane], a0, a1);
                    float2 t0 = *reinterpret_cast<const float2*>(&g_HN[(ll)d * 256 + 2 * lane]);
                    float2 t1 = *reinterpret_cast<const float2*>(&g_HN[(ll)d * 256 + 64 + 2 * lane]);
                    fi0 = t0.x; fi1 = t0.y; si0 = t1.x; si1 = t1.y;
                    a0 = 0.f; a1 = 0.f;
                    dprev = d;
                }
                float2 fj = *reinterpret_cast<const float2*>(&g_HN[(ll)s * 256 + 128 + 2 * lane]);
                float2 sj = *reinterpret_cast<const float2*>(&g_HN[(ll)s * 256 + 192 + 2 * lane]);
                float2 ef = *reinterpret_cast<const float2*>(&EW_s[e * 128 + 2 * lane]);
                float2 es = *reinterpret_cast<const float2*>(&EW_s[e * 128 + 64 + 2 * lane]);
                a0 += sigmoid_f(ef.x + fi0 + fj.x) * softplus_f(es.x + si0 + sj.x);
                a1 += sigmoid_f(ef.y + fi1 + fj.y) * softplus_f(es.y + si1 + sj.y);
            }
            if (dprev >= 0) red2(&g_acc[(ll)dprev * HD + 2 * lane], a0, a1);
        }
    }
}

// ---------------- BN stats ----------------
__global__ void stats_kernel(int a) {
    __shared__ float s_s[HD], s_q[HD];
    int tid = threadIdx.x;
    if (tid < HD) { s_s[tid] = 0.f; s_q[tid] = 0.f; }
    __syncthreads();
    int col4 = tid & 15;
    float4 ls = make_float4(0.f, 0.f, 0.f, 0.f), lq = ls;
    const float4* acc4 = reinterpret_cast<const float4*>(g_acc);
    for (int idx4 = blockIdx.x * blockDim.x + tid; idx4 < NN * 16; idx4 += gridDim.x * blockDim.x) {
        float4 v = acc4[idx4];
        ls.x += v.x; lq.x = fmaf(v.x, v.x, lq.x);
        ls.y += v.y; lq.y = fmaf(v.y, v.y, lq.y);
        ls.z += v.z; lq.z = fmaf(v.z, v.z, lq.z);
        ls.w += v.w; lq.w = fmaf(v.w, v.w, lq.w);
    }
    atomicAdd(&s_s[col4 * 4 + 0], ls.x); atomicAdd(&s_q[col4 * 4 + 0], lq.x);
    atomicAdd(&s_s[col4 * 4 + 1], ls.y); atomicAdd(&s_q[col4 * 4 + 1], lq.y);
    atomicAdd(&s_s[col4 * 4 + 2], ls.z); atomicAdd(&s_q[col4 * 4 + 2], lq.z);
    atomicAdd(&s_s[col4 * 4 + 3], ls.w); atomicAdd(&s_q[col4 * 4 + 3], lq.w);
    __syncthreads();
    if (tid < HD) {
        atomicAdd(&g_sum[a * HD + tid], s_s[tid]);
        atomicAdd(&g_sumsq[a * HD + tid], s_q[tid]);
    }
}

// ---------------- BN normalize (+relu) (+next residual) (+pooling) ----------------
__global__ void bn_kernel(const float* __restrict__ gamma, const float* __restrict__ beta,
                          int a, int do_relu, int write_acc, int do_pool,
                          const int* __restrict__ batch) {
    int idx4 = blockIdx.x * blockDim.x + threadIdx.x;
    if (idx4 >= NN * 16) return;
    int col4 = idx4 & 15;
    int node = idx4 >> 4;
    const float invn = 1.0f / (float)NN;
    float4 su = reinterpret_cast<const float4*>(g_sum)[a * 16 + col4];
    float4 sq = reinterpret_cast<const float4*>(g_sumsq)[a * 16 + col4];
    float4 ga = reinterpret_cast<const float4*>(gamma)[col4];
    float4 be = reinterpret_cast<const float4*>(beta)[col4];
    float4 v = reinterpret_cast<const float4*>(g_acc)[idx4];
    #pragma unroll
    for (int c = 0; c < 4; c++) {
        float mu = (&su.x)[c] * invn;
        float var = fmaxf((&sq.x)[c] * invn - mu * mu, 0.f);
        float y = ((&v.x)[c] - mu) * rsqrtf(var + BN_EPS) * (&ga.x)[c] + (&be.x)[c];
        if (do_relu) y = fmaxf(y, 0.f);
        (&v.x)[c] = y;
    }
    reinterpret_cast<float4*>(g_h)[idx4] = v;
    if (write_acc) reinterpret_cast<float4*>(g_acc)[idx4] = v;
    if (do_pool) {
        int b = batch[node];
        red4(&g_gsum[b * HD + col4 * 4], v);
        if (col4 == 0) atomicAdd(&g_gcnt[b], 1.0f);
    }
}

// ---------------- final MLP ----------------
__global__ void mlp_kernel(const float* __restrict__ W1, const float* __restrict__ b1,
                           const float* __restrict__ W2, const float* __restrict__ b2,
                           const float* __restrict__ Wo, const float* __restrict__ bo,
                           float* __restrict__ out) {
    __shared__ float sW1[HD * HD], sW2[HD * HD], sWo[HD], sb1[HD], sb2[HD];
    int tid = threadIdx.x;
    for (int i = tid; i < HD * HD; i += blockDim.x) { sW1[i] = W1[i]; sW2[i] = W2[i]; }
    if (tid < HD) { sWo[tid] = Wo[tid]; sb1[tid] = b1[tid]; sb2[tid] = b2[tid]; }
    __syncthreads();
    if (tid < NG) {
        float inv = 1.0f / fmaxf(g_gcnt[tid], 1.0f);
        float v[HD], y[HD];
        #pragma unroll
        for (int k = 0; k < HD; k++) v[k] = g_gsum[tid * HD + k] * inv;
        #pragma unroll 1
        for (int j = 0; j < HD; j++) {
            float s = sb1[j];
            #pragma unroll
            for (int k = 0; k < HD; k++) s = fmaf(v[k], sW1[k * HD + j], s);
            y[j] = softplus_f(s);
        }
        float o = bo[0];
        #pragma unroll 1
        for (int j = 0; j < HD; j++) {
            float s = sb2[j];
            #pragma unroll
            for (int k = 0; k < HD; k++) s = fmaf(y[k], sW2[k * HD + j], s);
            o = fmaf(softplus_f(s), sWo[j], o);
        }
        out[tid] = o;
    }
}

// ---------------- host launcher ----------------
template <int K, int NC, int CT, int RT, int RPT>
static void launch_gemm(const float* A, const float* B, const float* bias, float* C,
                        int M, int ldb, int ldc, int nsplit) {
    constexpr int TR = RT * RPT;
    constexpr int KP = K + 1;
    static_assert(CT * 8 == NC, "col threads x 8 must equal NC");
    size_t sm = (size_t)(K * NC + TR * KP) * sizeof(float);
    if (sm > 48 * 1024) {
        cudaFuncSetAttribute(gemm_bias_kernel<K, NC, CT, RT, RPT>,
                             cudaFuncAttributeMaxDynamicSharedMemorySize, (int)sm);
    }
    dim3 grid((M + TR - 1) / TR, nsplit);
    gemm_bias_kernel<K, NC, CT, RT, RPT><<<grid, CT * RT, sm>>>(A, B, bias, C, M, ldb, ldc);
}

extern "C" void kernel_launch(void* const* d_in, const int* in_sizes, int n_in,
                              void* d_out, int out_size) {
    const float* x         = (const float*)d_in[0];
    const float* edge_attr = (const float*)d_in[1];
    const int*   ei        = (const int*)d_in[2];
    const int*   batch     = (const int*)d_in[3];
    const float* W_emb1    = (const float*)d_in[4];
    const float* b_emb1    = (const float*)d_in[5];
    const float* W_emb2    = (const float*)d_in[6];
    const float* b_emb2    = (const float*)d_in[7];
    const float* Wf        = (const float*)d_in[8];
    const float* bf        = (const float*)d_in[9];
    const float* Ws        = (const float*)d_in[10];
    const float* bs        = (const float*)d_in[11];
    const float* gamma     = (const float*)d_in[12];
    const float* beta      = (const float*)d_in[13];
    const float* W1        = (const float*)d_in[14];
    const float* b1        = (const float*)d_in[15];
    const float* W2        = (const float*)d_in[16];
    const float* b2        = (const float*)d_in[17];
    const float* Wo        = (const float*)d_in[18];
    const float* bo        = (const float*)d_in[19];
    float* out = (float*)d_out;

    float *p_h, *p_Wce, *p_bce, *p_Wnode, *p_HN;
    cudaGetSymbolAddress((void**)&p_h, g_h);
    cudaGetSymbolAddress((void**)&p_Wce, g_Wce);
    cudaGetSymbolAddress((void**)&p_bce, g_bce);
    cudaGetSymbolAddress((void**)&p_Wnode, g_Wnode);
    cudaGetSymbolAddress((void**)&p_HN, g_HN);

    // fold weights + zero counters/stats
    prep_kernel<<<255, 256>>>(W_emb2, b_emb2, Wf, bf, Ws, bs);
    zero_kernel<<<NBLK, 256>>>();

    // sort edges by dst (counting sort) + permute edge_attr
    hist_kernel<<<(NE + 255) / 256, 256>>>(ei);
    scan1_kernel<<<NBLK, 256>>>();
    scan2_kernel<<<1, 256>>>();
    scan3_kernel<<<NBLK, 256>>>();
    scatter_kernel<<<(NE + 255) / 256, 256>>>(ei);
    permute_ea_kernel<<<1600, 256>>>(edge_attr);

    // h0 = x @ W_emb1 + b_emb1
    launch_gemm<FX, HD, 8, 32, 4>(x, W_emb1, b_emb1, p_h, NN, HD, HD, 1);
    copy_kernel<<<(NN * 16 + 255) / 256, 256>>>();

    // fused edge kernel smem: Ws(5248) + A(2788) + EW(8192) floats + 128 ints
    const int fe_smem = (FE * 128 + FE * APAD + EPB * 128) * 4 + 2 * EPB * 4;
    cudaFuncSetAttribute(fused_edge_kernel,
                         cudaFuncAttributeMaxDynamicSharedMemorySize, fe_smem);

    for (int a = 0; a < NCV; a++) {
        launch_gemm<HD, 2 * HD, 16, 16, 8>(p_h, p_Wnode + (ll)a * HD * 4 * HD,
                                           nullptr, p_HN, NN, 4 * HD, 4 * HD, 2);
        fused_edge_kernel<<<1184, 256, fe_smem>>>(p_Wce + a * FE * 2 * HD,
                                                  p_bce + a * 2 * HD);
        stats_kernel<<<296, 256>>>(a);
        bn_kernel<<<(NN * 16 + 255) / 256, 256>>>(gamma + a * HD, beta + a * HD, a,
                                                  a < NCV - 1 ? 1 : 0,
                                                  a < NCV - 1 ? 1 : 0,
                                                  a == NCV - 1 ? 1 : 0, batch);
    }

    mlp_kernel<<<1, 128>>>(W1, b1, W2, b2, Wo, bo, out);
}